// round 11
// baseline (speedup 1.0000x reference)
#include <cuda_runtime.h>
#include <math.h>

#define GRID_N   16
#define IN_DIM   64
#define OUT_DIM  64
#define BATCH    1024
#define NCOEF    19

#define BT 32                 // batch tile (warp lanes = b)
#define OB 2                  // o-columns per block
#define THREADS 128           // 4 warps -> fine-grained CTAs, 8 resident/SM

#define CS_F     (OB * IN_DIM * NCOEF)     // 2432 floats coef tile [oo][i][19]
#define S4_Q4    (OB * BT * 16)            // 1024 float4 result buffer
// union region: xs tile [32][17] f4 (544) | S4 (1024)  -> 1024 f4
#define SMEM_BYTES (CS_F * 4 + S4_Q4 * 16)   // 9728 + 16384 = 26112 B -> 8 CTAs/SM

__global__ __launch_bounds__(THREADS, 8)
void kan_kernel(const float* __restrict__ x,
                const float* __restrict__ coef,
                const float* __restrict__ grid,
                float* __restrict__ out) {
    extern __shared__ float sm[];
    float*  cs  = sm;                          // coef [oo][i][19]
    float4* xs4 = (float4*)(sm + CS_F);        // phase A: x tile [b][i4] pitch 17
    float4* S4  = (float4*)(sm + CS_F);        // phase B: results (same region)

    const int tid  = threadIdx.x;
    const int b0   = (blockIdx.x & 31) * BT;   // 32 batch tiles
    const int o0   = (blockIdx.x >> 5) * OB;   // 32 o-chunks
    const int lane = tid & 31;                 // -> b
    const int warp = tid >> 5;                 // -> i-group of 16 (4 quads)

    // ---- Stage coef tile + x tile (coalesced LDG.128).
    {
        const float4* src = (const float4*)(coef + (size_t)o0 * IN_DIM * NCOEF);
        #pragma unroll
        for (int t = tid; t < CS_F / 4; t += THREADS)
            ((float4*)cs)[t] = src[t];
        #pragma unroll
        for (int k = 0; k < 4; k++) {          // 512 f4 of x, 4 per thread
            int idx = tid + k * THREADS;
            int row = idx >> 4, col = idx & 15;
            xs4[row * 17 + col] = ((const float4*)x)[(size_t)(b0 + row) * 16 + col];
        }
    }
    const float g3    = grid[3];
    const float inv_h = 1.0f / (grid[4] - g3);
    const float k6    = 1.0f / 6.0f;
    __syncthreads();

    // ---- Pull this thread's 4 x-quads into registers (xs region is reused below).
    float4 xq[4];
    #pragma unroll
    for (int g = 0; g < 4; g++)
        xq[g] = xs4[lane * 17 + warp * 4 + g];  // LDS.128, pitch-17 conflict-free
    __syncthreads();   // xs fully consumed -> region becomes S4

    // ---- Compute per quad: weights (from registers) + conflict-free SMEM gathers.
    #pragma unroll
    for (int g = 0; g < 4; g++) {
        const int i4 = warp * 4 + g;
        float w0[4], w1[4], w2[4], w3[4];
        int   base[4];
        #pragma unroll
        for (int j = 0; j < 4; j++) {
            const float xv = (j == 0) ? xq[g].x : (j == 1) ? xq[g].y
                           : (j == 2) ? xq[g].z : xq[g].w;
            float t = (xv - g3) * inv_h;
            int i0 = (int)floorf(t);
            i0 = min(GRID_N - 1, max(0, i0));
            const float u  = t - (float)i0;
            const float om = 1.0f - u;
            const float u2 = u * u;
            w0[j] = om * om * om * k6;
            w3[j] = u2 * u * k6;
            w1[j] = fmaf(u2, fmaf(0.5f, u, -1.0f), 2.0f / 3.0f);
            w2[j] = 1.0f - w0[j] - w1[j] - w3[j];
            base[j] = (i4 * 4 + j) * NCOEF + i0;
        }
        #pragma unroll
        for (int oo = 0; oo < OB; oo++) {
            const float* c = cs + oo * (IN_DIM * NCOEF);
            float4 r;   // lanes=b: 19-word windows -> bank-conflict-free scalar LDS
            r.x = fmaf(w3[0], c[base[0] + 3], fmaf(w2[0], c[base[0] + 2],
                  fmaf(w1[0], c[base[0] + 1], w0[0] * c[base[0]])));
            r.y = fmaf(w3[1], c[base[1] + 3], fmaf(w2[1], c[base[1] + 2],
                  fmaf(w1[1], c[base[1] + 1], w0[1] * c[base[1]])));
            r.z = fmaf(w3[2], c[base[2] + 3], fmaf(w2[2], c[base[2] + 2],
                  fmaf(w1[2], c[base[2] + 1], w0[2] * c[base[2]])));
            r.w = fmaf(w3[3], c[base[3] + 3], fmaf(w2[3], c[base[3] + 2],
                  fmaf(w1[3], c[base[3] + 1], w0[3] * c[base[3]])));
            // XOR swizzle (bijective per row): write col = i4 ^ (lane&15).
            S4[(oo * BT + lane) * 16 + (i4 ^ (lane & 15))] = r;
        }
    }
    __syncthreads();

    // ---- Store: 1024 float4, 8/thread; contiguous 256B rows, coalesced STG.128.
    #pragma unroll
    for (int k = 0; k < 8; k++) {
        int t   = tid + k * THREADS;
        int i4s = t & 15;
        int oo  = (t >> 4) & 1;
        int bb  = t >> 5;
        float4 v = S4[(oo * BT + bb) * 16 + (i4s ^ (bb & 15))];
        reinterpret_cast<float4*>(out)[
            ((size_t)(b0 + bb) * OUT_DIM + (o0 + oo)) * (IN_DIM / 4) + i4s] = v;
    }
}

extern "C" void kernel_launch(void* const* d_in, const int* in_sizes, int n_in,
                              void* d_out, int out_size) {
    const float* x    = (const float*)d_in[0];
    const float* coef = (const float*)d_in[1];
    const float* grid = (const float*)d_in[2];
    float* out        = (float*)d_out;

    cudaFuncSetAttribute(kan_kernel, cudaFuncAttributeMaxDynamicSharedMemorySize,
                         SMEM_BYTES);
    kan_kernel<<<(BATCH / BT) * (OUT_DIM / OB), THREADS, SMEM_BYTES>>>(x, coef, grid, out);
}

// round 13
// speedup vs baseline: 1.0239x; 1.0239x over previous
#include <cuda_runtime.h>
#include <math.h>

#define GRID_N   16
#define IN_DIM   64
#define OUT_DIM  64
#define BATCH    1024
#define NCOEF    19

#define BT 32                 // batch tile (warp lanes = b)
#define OB 2                  // o-columns per block
#define IB 32                 // i-columns per block (half of IN_DIM)
#define THREADS 128

#define CS_F     (OB * IB * NCOEF)         // 1216 floats coef tile [oo][il][19]
#define CS_Q4    (CS_F / 4)                // 304
#define S4_Q4    (OB * BT * 8)             // 512 float4 (union w/ xs tile 288 f4)
#define SMEM_BYTES (CS_F * 4 + S4_Q4 * 16) // 4864 + 8192 = 13056 -> 12+ CTAs/SM

__global__ __launch_bounds__(THREADS, 12)
void kan_kernel(const float* __restrict__ x,
                const float* __restrict__ coef,
                const float* __restrict__ grid,
                float* __restrict__ out) {
    extern __shared__ float sm[];
    float*  cs  = sm;                        // coef [oo][il][19]
    float4* xs4 = (float4*)(sm + CS_F);      // phase A: x tile [b][8] pitch 9
    float4* S4  = (float4*)(sm + CS_F);      // phase B: results (same region)

    const int tid  = threadIdx.x;
    const int bid  = blockIdx.x;
    const int b0   = (bid & 31) * BT;        // 32 batch tiles
    const int rest = bid >> 5;               // 0..63
    const int o0   = (rest >> 1) * OB;       // 32 o-chunks
    const int ih   = rest & 1;               // i-half: global i = ih*32 + il
    const int lane = tid & 31;               // -> b
    const int warp = tid >> 5;               // -> 8 local i's (2 quads)

    // ---- Stage coef half-rows + x half-tile (coalesced LDG.128).
    {
        // per-(o,ih) half-row block = 32*19 floats = 152 f4, f4-aligned (608%4==0)
        #pragma unroll
        for (int t = tid; t < CS_Q4; t += THREADS) {
            int oo  = (t < 152) ? 0 : 1;
            int rem = t - oo * 152;
            ((float4*)cs)[oo * 152 + rem] =
                ((const float4*)coef)[152 * (2 * (o0 + oo) + ih) + rem];
        }
        #pragma unroll
        for (int k = 0; k < 2; k++) {        // 256 f4 of x, 2 per thread
            int idx = tid + k * THREADS;
            int row = idx >> 3, col = idx & 7;
            xs4[row * 9 + col] =
                ((const float4*)x)[(size_t)(b0 + row) * 16 + ih * 8 + col];
        }
    }
    const float g3    = grid[3];
    const float inv_h = 1.0f / (grid[4] - g3);
    const float k6    = 1.0f / 6.0f;
    __syncthreads();

    // ---- Pull this thread's 2 x-quads into registers, then free the region.
    float4 xq[2];
    #pragma unroll
    for (int g = 0; g < 2; g++)
        xq[g] = xs4[lane * 9 + warp * 2 + g];   // pitch 9: conflict-free LDS.128
    __syncthreads();   // xs consumed -> region becomes S4

    // ---- Compute: per quad weights (amortized over OB) + conflict-free gathers.
    #pragma unroll
    for (int g = 0; g < 2; g++) {
        const int i4 = warp * 2 + g;            // local f4-column 0..7
        float w0[4], w1[4], w2[4], w3[4];
        int   base[4];
        #pragma unroll
        for (int j = 0; j < 4; j++) {
            const float xv = (j == 0) ? xq[g].x : (j == 1) ? xq[g].y
                           : (j == 2) ? xq[g].z : xq[g].w;
            float t = (xv - g3) * inv_h;
            int i0 = (int)floorf(t);
            i0 = min(GRID_N - 1, max(0, i0));
            const float u  = t - (float)i0;
            const float om = 1.0f - u;
            const float u2 = u * u;
            w0[j] = om * om * om * k6;
            w3[j] = u2 * u * k6;
            w1[j] = fmaf(u2, fmaf(0.5f, u, -1.0f), 2.0f / 3.0f);
            w2[j] = 1.0f - w0[j] - w1[j] - w3[j];
            base[j] = (i4 * 4 + j) * NCOEF + i0;
        }
        #pragma unroll
        for (int oo = 0; oo < OB; oo++) {
            const float* c = cs + oo * (IB * NCOEF);
            float4 r;   // lanes=b, 19-word windows -> bank-conflict-free
            r.x = fmaf(w3[0], c[base[0] + 3], fmaf(w2[0], c[base[0] + 2],
                  fmaf(w1[0], c[base[0] + 1], w0[0] * c[base[0]])));
            r.y = fmaf(w3[1], c[base[1] + 3], fmaf(w2[1], c[base[1] + 2],
                  fmaf(w1[1], c[base[1] + 1], w0[1] * c[base[1]])));
            r.z = fmaf(w3[2], c[base[2] + 3], fmaf(w2[2], c[base[2] + 2],
                  fmaf(w1[2], c[base[2] + 1], w0[2] * c[base[2]])));
            r.w = fmaf(w3[3], c[base[3] + 3], fmaf(w2[3], c[base[3] + 2],
                  fmaf(w1[3], c[base[3] + 1], w0[3] * c[base[3]])));
            // XOR swizzle (3-bit, bijective per row).
            S4[(oo * BT + lane) * 8 + (i4 ^ (lane & 7))] = r;
        }
    }
    __syncthreads();

    // ---- Store: 512 f4, 4/thread; 128B contiguous half-rows, coalesced STG.128.
    #pragma unroll
    for (int k = 0; k < 4; k++) {
        int t   = tid + k * THREADS;
        int i4s = t & 7;
        int oo  = (t >> 3) & 1;
        int bb  = t >> 4;
        float4 v = S4[(oo * BT + bb) * 8 + (i4s ^ (bb & 7))];
        reinterpret_cast<float4*>(out)[
            ((size_t)(b0 + bb) * OUT_DIM + (o0 + oo)) * (IN_DIM / 4) + ih * 8 + i4s] = v;
    }
}

extern "C" void kernel_launch(void* const* d_in, const int* in_sizes, int n_in,
                              void* d_out, int out_size) {
    const float* x    = (const float*)d_in[0];
    const float* coef = (const float*)d_in[1];
    const float* grid = (const float*)d_in[2];
    float* out        = (float*)d_out;

    cudaFuncSetAttribute(kan_kernel, cudaFuncAttributeMaxDynamicSharedMemorySize,
                         SMEM_BYTES);
    kan_kernel<<<(BATCH / BT) * (OUT_DIM / OB) * (IN_DIM / IB), THREADS, SMEM_BYTES>>>(
        x, coef, grid, out);
}